// round 6
// baseline (speedup 1.0000x reference)
#include <cuda_runtime.h>
#include <cstdint>

#define BB 128
#define SS 4096
#define TT 64

// Scratch (no cudaMalloc allowed)
__device__ float g_res[BB];

// ---------------- packed f32x2 helpers ----------------
__device__ __forceinline__ unsigned long long pack2(float lo, float hi) {
    unsigned long long r;
    asm("mov.b64 %0, {%1, %2};" : "=l"(r) : "f"(lo), "f"(hi));
    return r;
}
__device__ __forceinline__ void unpack2(unsigned long long p, float& lo, float& hi) {
    asm("mov.b64 {%0, %1}, %2;" : "=f"(lo), "=f"(hi) : "l"(p));
}
__device__ __forceinline__ void fma2(unsigned long long& d, unsigned long long a, unsigned long long b) {
    asm("fma.rn.f32x2 %0, %1, %2, %0;" : "+l"(d) : "l"(a), "l"(b));
}
__device__ __forceinline__ unsigned long long mul2(unsigned long long a, unsigned long long b) {
    unsigned long long d;
    asm("mul.rn.f32x2 %0, %1, %2;" : "=l"(d) : "l"(a), "l"(b));
    return d;
}
__device__ __forceinline__ unsigned long long add2(unsigned long long a, unsigned long long b) {
    unsigned long long d;
    asm("add.rn.f32x2 %0, %1, %2;" : "=l"(d) : "l"(a), "l"(b));
    return d;
}

// Named barrier for the 64 scan threads (warps 0-1) only.
__device__ __forceinline__ void barrier64() {
    asm volatile("bar.sync 1, 64;" ::: "memory");
}

// ---------------- one forward-scan step ----------------
// u'[j] = (sum_i u[i] * E[i][j]) * gex[j] * 2^-e,  eacc += e,  e = exponent(u[0])
__device__ __forceinline__ void crf_step(const unsigned long long (&e2)[32],
                                         const float* __restrict__ ubuf_r,
                                         float* __restrict__ ubuf_w,
                                         int j, float gex, float& v, int& eacc) {
    barrier64();
    // Broadcast-load previous u (64 floats) as 32 f32x2 pairs via LDS.128
    unsigned long long uu[32];
#pragma unroll
    for (int q = 0; q < 16; q++) {
        ulonglong2 p = *reinterpret_cast<const ulonglong2*>(ubuf_r + 4 * q);
        uu[2 * q]     = p.x;
        uu[2 * q + 1] = p.y;
    }
    // Exact power-of-2 rescale: r = 2^-(E-127), C += (E-127)*ln2 (accumulated as int)
    unsigned ub = (unsigned)uu[0];           // low word = u[0] bits (u[0] > 0 always)
    int E = (int)(ub >> 23);
    eacc += E - 127;
    float r = __uint_as_float((unsigned)(254 - E) << 23);
    float gr = gex * r;

    unsigned long long a0 = mul2(uu[0], e2[0]);
    unsigned long long a1 = mul2(uu[1], e2[1]);
    unsigned long long a2 = mul2(uu[2], e2[2]);
    unsigned long long a3 = mul2(uu[3], e2[3]);
#pragma unroll
    for (int i = 4; i < 32; i += 4) {
        fma2(a0, uu[i],     e2[i]);
        fma2(a1, uu[i + 1], e2[i + 1]);
        fma2(a2, uu[i + 2], e2[i + 2]);
        fma2(a3, uu[i + 3], e2[i + 3]);
    }
    a0 = add2(a0, a1);
    a2 = add2(a2, a3);
    a0 = add2(a0, a2);
    float lo, hi;
    unpack2(a0, lo, hi);
    v = (lo + hi) * gr;
    ubuf_w[j] = v;
}

// ---------------- fused kernel: length + scan (warps 0-1) + numerator (warps 2-3) ----------------
__global__ void __launch_bounds__(128, 1)
crf_fused_kernel(const float* __restrict__ logits,
                 const int* __restrict__ tags,
                 const void* __restrict__ mask,
                 const float* __restrict__ trans,
                 const float* __restrict__ start_t,
                 const float* __restrict__ end_t) {
    const int b = blockIdx.x;
    const int tid = threadIdx.x;
    const float* lg = logits + (size_t)b * SS * TT;
    const int* tg = tags + b * SS;

    __shared__ __align__(16) float ubuf[2][TT];
    __shared__ float zz[2];
    __shared__ float snum[2];
    __shared__ float sden;
    __shared__ int scnt[4];
    __shared__ int sL;

    // ---- Phase 0: all 128 threads compute L = popcount(mask row) ----
    {
        const bool m32 = (((const int*)mask)[0] == 1);  // int32 vs uint8 layout
        int cnt = 0;
        if (m32) {
            const int4* mk = (const int4*)((const int*)mask + (size_t)b * SS);
            for (int q = tid; q < SS / 4; q += 128) {
                int4 w = mk[q];
                cnt += (w.x != 0) + (w.y != 0) + (w.z != 0) + (w.w != 0);
            }
        } else {
            const uint4* mk = (const uint4*)((const unsigned char*)mask + (size_t)b * SS);
            for (int q = tid; q < SS / 16; q += 128) {
                uint4 w = mk[q];  // bytes are 0/1, so popc counts set bytes
                cnt += __popc(w.x) + __popc(w.y) + __popc(w.z) + __popc(w.w);
            }
        }
#pragma unroll
        for (int o = 16; o > 0; o >>= 1) cnt += __shfl_down_sync(0xffffffffu, cnt, o);
        if ((tid & 31) == 0) scnt[tid >> 5] = cnt;
        __syncthreads();
        if (tid == 0) sL = (scnt[0] + scnt[1]) + (scnt[2] + scnt[3]);
        __syncthreads();
    }
    const int L = sL;

    if (tid < 64) {
        // ======== Warps 0-1: forward scan (denominator) ========
        const int j = tid;

        // E column j = exp(trans[:, j]) packed along i into f32x2
        unsigned long long e2[32];
#pragma unroll
        for (int i2 = 0; i2 < 32; i2++) {
            float a = __expf(trans[(2 * i2) * TT + j]);
            float c = __expf(trans[(2 * i2 + 1) * TT + j]);
            e2[i2] = pack2(a, c);
        }

        // alpha0 = start + logits[:,0] (linear domain)
        float v = __expf(start_t[j] + lg[j]);
        ubuf[1][j] = v;  // step t reads ubuf[t & 1]; t starts at 1
        int eacc = 0;

        // Two-stage pipeline: raw logit loaded 16 steps ahead, exp'd 8 steps ahead.
        float gq[8], raw[8];
#pragma unroll
        for (int k = 0; k < 8; k++)
            gq[k] = __expf(lg[(size_t)(1 + k) * TT + j]);     // steps 1..8
#pragma unroll
        for (int k = 0; k < 8; k++)
            raw[k] = lg[(size_t)(9 + k) * TT + j];            // steps 9..16

        int t = 1;
        for (; t + 8 <= L; t += 8) {
#pragma unroll
            for (int k = 0; k < 8; k++) {
                const int rb = (1 + k) & 1;  // t stays odd
                crf_step(e2, ubuf[rb], ubuf[rb ^ 1], j, gq[k], v, eacc);
                gq[k] = __expf(raw[k]);                        // for step t+k+8
                int nt = t + k + 16;                           // for step t+k+16
                nt = (nt < SS - 1) ? nt : (SS - 1);
                raw[k] = lg[(size_t)nt * TT + j];
            }
        }
        {
            const int rem = L - t;
#pragma unroll
            for (int k = 0; k < 8; k++) {
                if (k < rem) {
                    const int rb = (1 + k) & 1;
                    crf_step(e2, ubuf[rb], ubuf[rb ^ 1], j, gq[k], v, eacc);
                }
            }
        }

        // den = eacc*ln2 + log( sum_j v_j * exp(end_j) )
        float z = v * __expf(end_t[j]);
#pragma unroll
        for (int o = 16; o > 0; o >>= 1)
            z += __shfl_down_sync(0xffffffffu, z, o);
        if ((j & 31) == 0) zz[j >> 5] = z;
        barrier64();
        if (j == 0)
            sden = (float)eacc * 0.6931471805599453f + __logf(zz[0] + zz[1]);
    } else {
        // ======== Warps 2-3: numerator gather (no barriers; hidden under scan) ========
        const int lane = tid - 64;
        float nsum = 0.f;
#pragma unroll 4
        for (int k = 0; k < SS / 64; k++) {
            int t = lane + k * 64;
            if (t < L) {
                int tagt = tg[t];
                nsum += lg[(size_t)t * TT + tagt];
                if (t > 0) nsum += trans[tg[t - 1] * TT + tagt];
            }
        }
#pragma unroll
        for (int o = 16; o > 0; o >>= 1)
            nsum += __shfl_down_sync(0xffffffffu, nsum, o);
        if ((tid & 31) == 0) snum[(tid >> 5) - 2] = nsum;
    }

    __syncthreads();
    if (tid == 0) {
        float num = snum[0] + snum[1] + start_t[tg[0]] + end_t[tg[L - 1]];
        g_res[b] = num - sden;
    }
}

// ---------------- deterministic final reduction ----------------
__global__ void crf_finish_kernel(float* __restrict__ out) {
    const int i = threadIdx.x;  // 128 threads
    float d = g_res[i];
#pragma unroll
    for (int o = 16; o > 0; o >>= 1)
        d += __shfl_down_sync(0xffffffffu, d, o);
    __shared__ float ws[4];
    if ((i & 31) == 0) ws[i >> 5] = d;
    __syncthreads();
    if (i == 0) out[0] = (ws[0] + ws[1]) + (ws[2] + ws[3]);
}

// ---------------- launch ----------------
extern "C" void kernel_launch(void* const* d_in, const int* in_sizes, int n_in,
                              void* d_out, int out_size) {
    const float* logits = (const float*)d_in[0];
    const int* tags     = (const int*)d_in[1];
    const void* mask    = d_in[2];
    const float* trans  = (const float*)d_in[3];
    const float* startt = (const float*)d_in[4];
    const float* endt   = (const float*)d_in[5];
    float* out = (float*)d_out;

    crf_fused_kernel<<<BB, 128>>>(logits, tags, mask, trans, startt, endt);
    crf_finish_kernel<<<1, 128>>>(out);
}

// round 7
// speedup vs baseline: 1.3047x; 1.3047x over previous
#include <cuda_runtime.h>
#include <cstdint>

#define BB 128
#define SS 4096
#define TT 64

// Scratch (no cudaMalloc allowed)
__device__ float g_num[BB];
__device__ float g_den[BB];
__device__ int   g_len[BB];

// ---------------- packed f32x2 helpers ----------------
__device__ __forceinline__ unsigned long long pack2(float lo, float hi) {
    unsigned long long r;
    asm("mov.b64 %0, {%1, %2};" : "=l"(r) : "f"(lo), "f"(hi));
    return r;
}
__device__ __forceinline__ void unpack2(unsigned long long p, float& lo, float& hi) {
    asm("mov.b64 {%0, %1}, %2;" : "=f"(lo), "=f"(hi) : "l"(p));
}
__device__ __forceinline__ void fma2(unsigned long long& d, unsigned long long a, unsigned long long b) {
    asm("fma.rn.f32x2 %0, %1, %2, %0;" : "+l"(d) : "l"(a), "l"(b));
}
__device__ __forceinline__ unsigned long long mul2(unsigned long long a, unsigned long long b) {
    unsigned long long d;
    asm("mul.rn.f32x2 %0, %1, %2;" : "=l"(d) : "l"(a), "l"(b));
    return d;
}
__device__ __forceinline__ unsigned long long add2(unsigned long long a, unsigned long long b) {
    unsigned long long d;
    asm("add.rn.f32x2 %0, %1, %2;" : "=l"(d) : "l"(a), "l"(b));
    return d;
}

// ---------------- kernel 1: numerator + lengths (1024 threads for MLP) ----------------
__global__ void __launch_bounds__(1024)
crf_numer_kernel(const float* __restrict__ logits,
                 const int* __restrict__ tags,
                 const void* __restrict__ mask,
                 const float* __restrict__ trans,
                 const float* __restrict__ start_t,
                 const float* __restrict__ end_t) {
    const int b = blockIdx.x;
    const int tid = threadIdx.x;
    const int NT = 1024;

    const bool m32 = (((const int*)mask)[0] == 1);  // int32 vs uint8 layout
    const float* lg = logits + (size_t)b * SS * TT;
    const int* tg = tags + b * SS;
    const unsigned char* mk8 = ((const unsigned char*)mask) + (size_t)b * SS;
    const int* mk32 = ((const int*)mask) + (size_t)b * SS;

    float sum = 0.f;
    int cnt = 0;
#pragma unroll
    for (int k = 0; k < SS / NT; k++) {
        int t = tid + k * NT;
        int m = m32 ? (mk32[t] != 0) : (mk8[t] != 0);
        cnt += m;
        if (m) {
            int tagt = tg[t];
            sum += lg[(size_t)t * TT + tagt];
            if (t > 0) sum += trans[tg[t - 1] * TT + tagt];
        }
    }
#pragma unroll
    for (int o = 16; o > 0; o >>= 1) {
        sum += __shfl_down_sync(0xffffffffu, sum, o);
        cnt += __shfl_down_sync(0xffffffffu, cnt, o);
    }
    __shared__ float ssum[32];
    __shared__ int scnt[32];
    if ((tid & 31) == 0) { ssum[tid >> 5] = sum; scnt[tid >> 5] = cnt; }
    __syncthreads();
    if (tid < 32) {
        float s2 = ssum[tid];
        int c2 = scnt[tid];
#pragma unroll
        for (int o = 16; o > 0; o >>= 1) {
            s2 += __shfl_down_sync(0xffffffffu, s2, o);
            c2 += __shfl_down_sync(0xffffffffu, c2, o);
        }
        if (tid == 0) {
            int L = c2;
            s2 += start_t[tg[0]] + end_t[tg[L - 1]];
            g_num[b] = s2;
            g_len[b] = L;
        }
    }
}

// ---------------- one forward-scan step ----------------
// u'[j] = (sum_i u[i] * E[i][j]) * gex[j] * 2^-e,  eacc += e,  e = exponent(u[0]) - 127
__device__ __forceinline__ void crf_step(const unsigned long long (&e2)[32],
                                         const float* __restrict__ ubuf_r,
                                         float* __restrict__ ubuf_w,
                                         int j, float gex, float& v, int& eacc) {
    __syncthreads();
    // Broadcast-load previous u (64 floats) as 32 f32x2 pairs via LDS.128
    unsigned long long uu[32];
#pragma unroll
    for (int q = 0; q < 16; q++) {
        ulonglong2 p = *reinterpret_cast<const ulonglong2*>(ubuf_r + 4 * q);
        uu[2 * q]     = p.x;
        uu[2 * q + 1] = p.y;
    }
    // Exact power-of-2 rescale (no MUFU): r = 2^-(E-127), eacc += E-127 (integer)
    unsigned ub = (unsigned)uu[0];           // low word = u[0] bits (u[0] > 0 always)
    int E = (int)(ub >> 23);
    eacc += E - 127;
    float r = __uint_as_float((unsigned)(254 - E) << 23);
    float gr = gex * r;

    unsigned long long a0 = mul2(uu[0], e2[0]);
    unsigned long long a1 = mul2(uu[1], e2[1]);
    unsigned long long a2 = mul2(uu[2], e2[2]);
    unsigned long long a3 = mul2(uu[3], e2[3]);
#pragma unroll
    for (int i = 4; i < 32; i += 4) {
        fma2(a0, uu[i],     e2[i]);
        fma2(a1, uu[i + 1], e2[i + 1]);
        fma2(a2, uu[i + 2], e2[i + 2]);
        fma2(a3, uu[i + 3], e2[i + 3]);
    }
    a0 = add2(a0, a1);
    a2 = add2(a2, a3);
    a0 = add2(a0, a2);
    float lo, hi;
    unpack2(a0, lo, hi);
    v = (lo + hi) * gr;
    ubuf_w[j] = v;
}

// ---------------- kernel 2: forward scan (denominator), 64 threads ----------------
__global__ void __launch_bounds__(64, 1)
crf_scan_kernel(const float* __restrict__ logits,
                const float* __restrict__ trans,
                const float* __restrict__ start_t,
                const float* __restrict__ end_t) {
    const int b = blockIdx.x;
    const int j = threadIdx.x;
    const float* lg = logits + (size_t)b * SS * TT;
    const int L = g_len[b];

    // E column j = exp(trans[:, j]) packed along i into f32x2
    unsigned long long e2[32];
#pragma unroll
    for (int i2 = 0; i2 < 32; i2++) {
        float a = __expf(trans[(2 * i2) * TT + j]);
        float c = __expf(trans[(2 * i2 + 1) * TT + j]);
        e2[i2] = pack2(a, c);
    }

    __shared__ __align__(16) float ubuf[2][TT];
    __shared__ float zz[2];

    // alpha0 = start + logits[:,0] (linear domain)
    float v = __expf(start_t[j] + lg[j]);
    ubuf[1][j] = v;  // step t reads ubuf[t & 1]; t starts at 1
    int eacc = 0;

    // Two-stage pipeline: raw logit loaded 16 steps ahead, exp'd 8 steps ahead.
    float gq[8], raw[8];
#pragma unroll
    for (int k = 0; k < 8; k++)
        gq[k] = __expf(lg[(size_t)(1 + k) * TT + j]);     // for steps 1..8
#pragma unroll
    for (int k = 0; k < 8; k++)
        raw[k] = lg[(size_t)(9 + k) * TT + j];            // for steps 9..16

    int t = 1;
    for (; t + 8 <= L; t += 8) {
#pragma unroll
        for (int k = 0; k < 8; k++) {
            const int rb = (1 + k) & 1;  // t stays odd
            crf_step(e2, ubuf[rb], ubuf[rb ^ 1], j, gq[k], v, eacc);
            gq[k] = __expf(raw[k]);                        // for step t+k+8
            int nt = t + k + 16;                           // for step t+k+16
            nt = (nt < SS - 1) ? nt : (SS - 1);
            raw[k] = lg[(size_t)nt * TT + j];
        }
    }
    {
        const int rem = L - t;
#pragma unroll
        for (int k = 0; k < 8; k++) {
            if (k < rem) {
                const int rb = (1 + k) & 1;
                crf_step(e2, ubuf[rb], ubuf[rb ^ 1], j, gq[k], v, eacc);
            }
        }
    }

    // den = eacc*ln2 + log( sum_j v_j * exp(end_j) )
    float z = v * __expf(end_t[j]);
#pragma unroll
    for (int o = 16; o > 0; o >>= 1)
        z += __shfl_down_sync(0xffffffffu, z, o);
    if ((j & 31) == 0) zz[j >> 5] = z;
    __syncthreads();
    if (j == 0)
        g_den[b] = (float)eacc * 0.6931471805599453f + __logf(zz[0] + zz[1]);
}

// ---------------- kernel 3: deterministic final reduction ----------------
__global__ void crf_finish_kernel(float* __restrict__ out) {
    const int i = threadIdx.x;  // 128 threads
    float d = g_num[i] - g_den[i];
#pragma unroll
    for (int o = 16; o > 0; o >>= 1)
        d += __shfl_down_sync(0xffffffffu, d, o);
    __shared__ float ws[4];
    if ((i & 31) == 0) ws[i >> 5] = d;
    __syncthreads();
    if (i == 0) out[0] = (ws[0] + ws[1]) + (ws[2] + ws[3]);
}

// ---------------- launch ----------------
extern "C" void kernel_launch(void* const* d_in, const int* in_sizes, int n_in,
                              void* d_out, int out_size) {
    const float* logits = (const float*)d_in[0];
    const int* tags     = (const int*)d_in[1];
    const void* mask    = d_in[2];
    const float* trans  = (const float*)d_in[3];
    const float* startt = (const float*)d_in[4];
    const float* endt   = (const float*)d_in[5];
    float* out = (float*)d_out;

    crf_numer_kernel<<<BB, 1024>>>(logits, tags, mask, trans, startt, endt);
    crf_scan_kernel<<<BB, 64>>>(logits, trans, startt, endt);
    crf_finish_kernel<<<1, 128>>>(out);
}

// round 8
// speedup vs baseline: 1.3523x; 1.0365x over previous
#include <cuda_runtime.h>
#include <cstdint>

#define BB 128
#define SS 4096
#define TT 64

// Scratch (no cudaMalloc allowed)
__device__ float g_num[BB];
__device__ float g_den[BB];
__device__ int   g_len[BB];

// ---------------- packed f32x2 helpers ----------------
__device__ __forceinline__ unsigned long long pack2(float lo, float hi) {
    unsigned long long r;
    asm("mov.b64 %0, {%1, %2};" : "=l"(r) : "f"(lo), "f"(hi));
    return r;
}
__device__ __forceinline__ void unpack2(unsigned long long p, float& lo, float& hi) {
    asm("mov.b64 {%0, %1}, %2;" : "=f"(lo), "=f"(hi) : "l"(p));
}
__device__ __forceinline__ void fma2(unsigned long long& d, unsigned long long a, unsigned long long b) {
    asm("fma.rn.f32x2 %0, %1, %2, %0;" : "+l"(d) : "l"(a), "l"(b));
}
__device__ __forceinline__ unsigned long long mul2(unsigned long long a, unsigned long long b) {
    unsigned long long d;
    asm("mul.rn.f32x2 %0, %1, %2;" : "=l"(d) : "l"(a), "l"(b));
    return d;
}
__device__ __forceinline__ unsigned long long add2(unsigned long long a, unsigned long long b) {
    unsigned long long d;
    asm("add.rn.f32x2 %0, %1, %2;" : "=l"(d) : "l"(a), "l"(b));
    return d;
}

// ---------------- kernel 1: numerator + lengths (1024 threads for MLP) ----------------
__global__ void __launch_bounds__(1024)
crf_numer_kernel(const float* __restrict__ logits,
                 const int* __restrict__ tags,
                 const void* __restrict__ mask,
                 const float* __restrict__ trans,
                 const float* __restrict__ start_t,
                 const float* __restrict__ end_t) {
    const int b = blockIdx.x;
    const int tid = threadIdx.x;
    const int NT = 1024;

    const bool m32 = (((const int*)mask)[0] == 1);  // int32 vs uint8 layout
    const float* lg = logits + (size_t)b * SS * TT;
    const int* tg = tags + b * SS;
    const unsigned char* mk8 = ((const unsigned char*)mask) + (size_t)b * SS;
    const int* mk32 = ((const int*)mask) + (size_t)b * SS;

    float sum = 0.f;
    int cnt = 0;
#pragma unroll
    for (int k = 0; k < SS / NT; k++) {
        int t = tid + k * NT;
        int m = m32 ? (mk32[t] != 0) : (mk8[t] != 0);
        cnt += m;
        if (m) {
            int tagt = tg[t];
            sum += lg[(size_t)t * TT + tagt];
            if (t > 0) sum += trans[tg[t - 1] * TT + tagt];
        }
    }
#pragma unroll
    for (int o = 16; o > 0; o >>= 1) {
        sum += __shfl_down_sync(0xffffffffu, sum, o);
        cnt += __shfl_down_sync(0xffffffffu, cnt, o);
    }
    __shared__ float ssum[32];
    __shared__ int scnt[32];
    if ((tid & 31) == 0) { ssum[tid >> 5] = sum; scnt[tid >> 5] = cnt; }
    __syncthreads();
    if (tid < 32) {
        float s2 = ssum[tid];
        int c2 = scnt[tid];
#pragma unroll
        for (int o = 16; o > 0; o >>= 1) {
            s2 += __shfl_down_sync(0xffffffffu, s2, o);
            c2 += __shfl_down_sync(0xffffffffu, c2, o);
        }
        if (tid == 0) {
            int L = c2;
            s2 += start_t[tg[0]] + end_t[tg[L - 1]];
            g_num[b] = s2;
            g_len[b] = L;
        }
    }
}

// ---------------- one forward-scan step (2-way i-split) ----------------
// Thread (j,p) computes sum_{i in [32p,32p+32)} u[i]*E[i][j]; partner lanes
// (tid^1) combine via shfl.bfly; p==0 applies exact pow2 rescale and stores.
// Shared u layout: floats [0,32) at idx 0..31, floats [32,64) at idx 36..67
// (16B stagger => even/odd lanes hit disjoint banks; both halves broadcast).
__device__ __forceinline__ void crf_step2(const unsigned long long (&e2)[16],
                                          const float* __restrict__ ubuf_r,
                                          float* __restrict__ ubuf_w,
                                          int p, int jj, float gex, int& eacc) {
    __syncthreads();
    const float* base = ubuf_r + 36 * p;
    unsigned long long uu[16];
#pragma unroll
    for (int q = 0; q < 8; q++) {
        ulonglong2 pr = *reinterpret_cast<const ulonglong2*>(base + 4 * q);
        uu[2 * q]     = pr.x;
        uu[2 * q + 1] = pr.y;
    }
    unsigned long long a0 = mul2(uu[0], e2[0]);
    unsigned long long a1 = mul2(uu[1], e2[1]);
#pragma unroll
    for (int i = 2; i < 16; i += 2) {
        fma2(a0, uu[i],     e2[i]);
        fma2(a1, uu[i + 1], e2[i + 1]);
    }
    a0 = add2(a0, a1);
    float lo, hi;
    unpack2(a0, lo, hi);
    float part = lo + hi;
    part += __shfl_xor_sync(0xffffffffu, part, 1);
    if (p == 0) {
        // Exact power-of-2 rescale from exponent of u[0] (p==0 lanes hold u[0])
        unsigned ub = (unsigned)uu[0];
        int E = (int)(ub >> 23);
        eacc += E - 127;
        float r = __uint_as_float((unsigned)(254 - E) << 23);
        ubuf_w[jj] = part * (gex * r);
    }
}

// ---------------- kernel 2: forward scan (denominator), 128 threads ----------------
__global__ void __launch_bounds__(128, 1)
crf_scan_kernel(const float* __restrict__ logits,
                const float* __restrict__ trans,
                const float* __restrict__ start_t,
                const float* __restrict__ end_t) {
    const int b = blockIdx.x;
    const int tid = threadIdx.x;
    const int j = tid >> 1;       // column
    const int p = tid & 1;        // i-half
    const int jj = (j < 32) ? j : j + 4;  // staggered store index
    const float* lg = logits + (size_t)b * SS * TT;
    const int L = g_len[b];

    // Half-column of E = exp(trans): i in [32p, 32p+32), packed f32x2
    unsigned long long e2[16];
#pragma unroll
    for (int q = 0; q < 16; q++) {
        int i0 = 32 * p + 2 * q;
        e2[q] = pack2(__expf(trans[i0 * TT + j]),
                      __expf(trans[(i0 + 1) * TT + j]));
    }

    __shared__ __align__(16) float ubuf[2][72];
    __shared__ float zz[2];

    // alpha0 = start + logits[:,0] (linear domain)
    if (p == 0) ubuf[1][jj] = __expf(start_t[j] + lg[j]);
    int eacc = 0;

    // Two-stage pipeline (p==0 lanes only): raw logit loaded 16 ahead, exp'd 8 ahead.
    float gq[8], raw[8];
    if (p == 0) {
#pragma unroll
        for (int k = 0; k < 8; k++)
            gq[k] = __expf(lg[(size_t)(1 + k) * TT + j]);
#pragma unroll
        for (int k = 0; k < 8; k++)
            raw[k] = lg[(size_t)(9 + k) * TT + j];
    }

    int t = 1;
    for (; t + 8 <= L; t += 8) {
#pragma unroll
        for (int k = 0; k < 8; k++) {
            const int rb = (1 + k) & 1;  // t stays odd
            crf_step2(e2, ubuf[rb], ubuf[rb ^ 1], p, jj, gq[k], eacc);
            if (p == 0) {
                gq[k] = __expf(raw[k]);              // for step t+k+8
                int nt = t + k + 16;                 // for step t+k+16
                nt = (nt < SS - 1) ? nt : (SS - 1);
                raw[k] = lg[(size_t)nt * TT + j];
            }
        }
    }
    {
        const int rem = L - t;
#pragma unroll
        for (int k = 0; k < 8; k++) {
            if (k < rem) {
                const int rb = (1 + k) & 1;
                crf_step2(e2, ubuf[rb], ubuf[rb ^ 1], p, jj, gq[k], eacc);
            }
        }
    }

    // den = eacc*ln2 + log( sum_j v_j * exp(end_j) ); final alpha in ubuf[L&1]
    __syncthreads();
    float z = 0.f;
    if (tid < 64) {
        int idx = (tid < 32) ? tid : tid + 4;
        z = ubuf[L & 1][idx] * __expf(end_t[tid]);
    }
#pragma unroll
    for (int o = 16; o > 0; o >>= 1)
        z += __shfl_down_sync(0xffffffffu, z, o);
    if (tid < 64 && (tid & 31) == 0) zz[tid >> 5] = z;
    __syncthreads();
    if (tid == 0)
        g_den[b] = (float)eacc * 0.6931471805599453f + __logf(zz[0] + zz[1]);
}

// ---------------- kernel 3: deterministic final reduction ----------------
__global__ void crf_finish_kernel(float* __restrict__ out) {
    const int i = threadIdx.x;  // 128 threads
    float d = g_num[i] - g_den[i];
#pragma unroll
    for (int o = 16; o > 0; o >>= 1)
        d += __shfl_down_sync(0xffffffffu, d, o);
    __shared__ float ws[4];
    if ((i & 31) == 0) ws[i >> 5] = d;
    __syncthreads();
    if (i == 0) out[0] = (ws[0] + ws[1]) + (ws[2] + ws[3]);
}

// ---------------- launch ----------------
extern "C" void kernel_launch(void* const* d_in, const int* in_sizes, int n_in,
                              void* d_out, int out_size) {
    const float* logits = (const float*)d_in[0];
    const int* tags     = (const int*)d_in[1];
    const void* mask    = d_in[2];
    const float* trans  = (const float*)d_in[3];
    const float* startt = (const float*)d_in[4];
    const float* endt   = (const float*)d_in[5];
    float* out = (float*)d_out;

    crf_numer_kernel<<<BB, 1024>>>(logits, tags, mask, trans, startt, endt);
    crf_scan_kernel<<<BB, 128>>>(logits, trans, startt, endt);
    crf_finish_kernel<<<1, 128>>>(out);
}